// round 7
// baseline (speedup 1.0000x reference)
#include <cuda_runtime.h>
#include <cstdint>

#define BB 2
#define N1 4096
#define N2 8192
#define NSPLIT 8
#define KSEL 16

// ---------------- scratch (__device__ globals: allowed) ----------------
__device__ __align__(16) float g_f1n [BB*N1*64];
__device__ __align__(16) float g_f2n [BB*N2*64];
__device__ __align__(16) float g_p2r [BB*N2*64];
__device__ __align__(16) float g_p2ro[BB*N2*64];
__device__ __align__(16) float g_p2z [BB*N2*64];
__device__ __align__(16) float g_gp1r[BB*N1*64];
__device__ __align__(16) float g_gp1z[BB*N1*64];
__device__ __align__(16) float g_p1o [BB*N1*64];
__device__ float g_cosv[BB*N1*NSPLIT*8];
__device__ int   g_cosi[BB*N1*NSPLIT*8];
__device__ float g_eucv[BB*N1*NSPLIT*8];
__device__ int   g_euci[BB*N1*NSPLIT*8];
__device__ int   g_idx [BB*N1*KSEL];

// ---------------- helpers ----------------
__device__ __forceinline__ void fma2(unsigned long long& d, unsigned long long a, unsigned long long b) {
    asm("fma.rn.f32x2 %0, %1, %2, %0;" : "+l"(d) : "l"(a), "l"(b));
}
__device__ __forceinline__ float hsum2(unsigned long long v) {
    return __uint_as_float((unsigned)v) + __uint_as_float((unsigned)(v >> 32));
}
__device__ __forceinline__ float leaky(float x) { return fmaxf(x, 0.1f * x); }
__device__ __forceinline__ float sigm(float x) { return 1.f / (1.f + __expf(-x)); }

__device__ __forceinline__ void top8_insert(float (&tv)[8], int (&ti)[8], float v, int j) {
    #pragma unroll
    for (int t = 0; t < 8; t++) {
        if (v > tv[t]) { float fv = tv[t]; int fj = ti[t]; tv[t] = v; ti[t] = j; v = fv; j = fj; }
    }
}

// 64x64 matvec, W rows padded to 68 floats in smem
__device__ __forceinline__ float matvec64(const float* __restrict__ W, const float* __restrict__ v, int o) {
    const ulonglong2* m2 = (const ulonglong2*)(W + o * 68);
    const ulonglong2* v2 = (const ulonglong2*)v;
    unsigned long long a0 = 0ull, a1 = 0ull, a2 = 0ull, a3 = 0ull;
    #pragma unroll
    for (int i = 0; i < 16; i += 2) {
        ulonglong2 m = m2[i],     x = v2[i];
        fma2(a0, m.x, x.x); fma2(a1, m.y, x.y);
        ulonglong2 mb = m2[i + 1], xb = v2[i + 1];
        fma2(a2, mb.x, xb.x); fma2(a3, mb.y, xb.y);
    }
    return (hsum2(a0) + hsum2(a1)) + (hsum2(a2) + hsum2(a3));
}

// ---------------- normalize: dst[b][n][c] = src[b][c][n] * rsqrt(sumsq+1e-8) ----------------
__global__ void k_normalize(const float* __restrict__ src_, float* __restrict__ dst_, int N) {
    __shared__ float s[64 * 65];
    __shared__ float inv[64];
    int b = blockIdx.y;
    int n0 = blockIdx.x * 64;
    const float* src = src_ + (size_t)b * 64 * N;
    for (int i = threadIdx.x; i < 4096; i += 256) {
        int c = i >> 6, n = i & 63;
        s[c * 65 + n] = src[(size_t)c * N + n0 + n];
    }
    __syncthreads();
    if (threadIdx.x < 64) {
        int n = threadIdx.x;
        float acc = 0.f;
        #pragma unroll
        for (int c = 0; c < 64; c++) { float v = s[c * 65 + n]; acc += v * v; }
        inv[n] = rsqrtf(acc + 1e-8f);
    }
    __syncthreads();
    float* dst = dst_ + ((size_t)b * N + n0) * 64;
    for (int i = threadIdx.x; i < 4096; i += 256) {
        int n = i >> 6, c = i & 63;
        dst[n * 64 + c] = s[c * 65 + n] * inv[n];
    }
}

// ---------------- project: out[b][n][o] = sum_c W[o][c]*P[b][c][n] ----------------
__global__ void __launch_bounds__(256) k_project(const float* __restrict__ P, const float* __restrict__ W,
                                                 float* __restrict__ out, int N) {
    __shared__ __align__(16) float s[64 * 68];    // s[n][c]
    __shared__ __align__(16) float Wsh[64 * 68];  // Wsh[o][c]
    int b = blockIdx.y;
    int n0 = blockIdx.x * 64;
    int t = threadIdx.x;
    for (int i = t; i < 4096; i += 256) {
        int c = i >> 6, n = i & 63;
        s[n * 68 + c] = P[((size_t)b * 64 + c) * N + n0 + n];
        Wsh[(i >> 6) * 68 + (i & 63)] = W[i];
    }
    __syncthreads();
    int o = t & 63, nb = t >> 6;
    float acc[16];
    #pragma unroll
    for (int j = 0; j < 16; j++) acc[j] = 0.f;
    const float4* w4 = (const float4*)(Wsh + o * 68);
    #pragma unroll
    for (int ci = 0; ci < 16; ci++) {
        float4 w = w4[ci];
        #pragma unroll
        for (int j = 0; j < 16; j++) {
            float4 v = ((const float4*)(s + (nb + 4 * j) * 68))[ci];
            acc[j] += w.x * v.x + w.y * v.y + w.z * v.z + w.w * v.w;
        }
    }
    float* dst = out + ((size_t)b * N + n0) * 64;
    #pragma unroll
    for (int j = 0; j < 16; j++)
        dst[(nb + 4 * j) * 64 + o] = acc[j];
}

// ---------------- cosine knn partial top-8 per split ----------------
__global__ void __launch_bounds__(128) k_cosknn() {
    __shared__ __align__(16) float s[64 * 68];
    int b = blockIdx.z, split = blockIdx.y;
    int q = blockIdx.x * 128 + threadIdx.x;
    ulonglong2 qr[16];
    const ulonglong2* qp = (const ulonglong2*)(g_f1n + ((size_t)b * N1 + q) * 64);
    #pragma unroll
    for (int i = 0; i < 16; i++) qr[i] = qp[i];
    float tv[8]; int ti[8];
    #pragma unroll
    for (int i = 0; i < 8; i++) { tv[i] = -1e30f; ti[i] = 0; }
    const int SPLITN = N2 / NSPLIT;
    int j0 = split * SPLITN;
    for (int tile = 0; tile < SPLITN / 64; tile++) {
        int jt = j0 + tile * 64;
        __syncthreads();
        for (int i = threadIdx.x; i < 4096; i += 128) {
            int cand = i >> 6, c = i & 63;
            s[cand * 68 + c] = g_f2n[((size_t)b * N2 + jt + cand) * 64 + c];
        }
        __syncthreads();
        for (int cc = 0; cc < 64; cc++) {
            const ulonglong2* cp = (const ulonglong2*)(s + cc * 68);
            unsigned long long a0 = 0ull, a1 = 0ull, a2 = 0ull, a3 = 0ull;
            #pragma unroll
            for (int i = 0; i < 16; i += 2) {
                ulonglong2 c2 = cp[i];
                fma2(a0, qr[i].x, c2.x);
                fma2(a1, qr[i].y, c2.y);
                ulonglong2 c3 = cp[i + 1];
                fma2(a2, qr[i + 1].x, c3.x);
                fma2(a3, qr[i + 1].y, c3.y);
            }
            float d = (hsum2(a0) + hsum2(a1)) + (hsum2(a2) + hsum2(a3));
            if (d > tv[7]) top8_insert(tv, ti, d, jt + cc);
        }
    }
    size_t base = (((size_t)b * N1 + q) * NSPLIT + split) * 8;
    #pragma unroll
    for (int t = 0; t < 8; t++) { g_cosv[base + t] = tv[t]; g_cosi[base + t] = ti[t]; }
}

// ---------------- euclidean knn partial top-8 per split ----------------
__global__ void __launch_bounds__(128) k_eucknn(const float* __restrict__ xyz1, const float* __restrict__ xyz2) {
    __shared__ float sx[1024], sy[1024], sz[1024];
    int b = blockIdx.z, split = blockIdx.y;
    int q = blockIdx.x * 128 + threadIdx.x;
    int j0 = split * 1024;
    const float* x2 = xyz2 + (size_t)b * 3 * N2;
    for (int i = threadIdx.x; i < 1024; i += 128) {
        sx[i] = x2[j0 + i]; sy[i] = x2[N2 + j0 + i]; sz[i] = x2[2 * N2 + j0 + i];
    }
    __syncthreads();
    const float* x1 = xyz1 + (size_t)b * 3 * N1;
    float qx = x1[q], qy = x1[N1 + q], qz = x1[2 * N1 + q];
    float tv[8]; int ti[8];
    #pragma unroll
    for (int i = 0; i < 8; i++) { tv[i] = -1e30f; ti[i] = 0; }
    for (int cc = 0; cc < 1024; cc++) {
        float dx = sx[cc] - qx, dy = sy[cc] - qy, dz = sz[cc] - qz;
        float d = -(dx * dx + dy * dy + dz * dz);
        if (d > tv[7]) top8_insert(tv, ti, d, j0 + cc);
    }
    size_t base = (((size_t)b * N1 + q) * NSPLIT + split) * 8;
    #pragma unroll
    for (int t = 0; t < 8; t++) { g_eucv[base + t] = tv[t]; g_euci[base + t] = ti[t]; }
}

// ---------------- merge split partials -> idx[q][16] ----------------
__global__ void k_merge() {
    int q = blockIdx.x * 256 + threadIdx.x;
    if (q >= BB * N1) return;
    size_t base = (size_t)q * (NSPLIT * 8);
    float tv[8]; int ti[8];
    #pragma unroll
    for (int i = 0; i < 8; i++) { tv[i] = -1e30f; ti[i] = 0; }
    for (int i = 0; i < NSPLIT * 8; i++) {
        float v = g_cosv[base + i];
        if (v > tv[7]) top8_insert(tv, ti, v, g_cosi[base + i]);
    }
    #pragma unroll
    for (int t = 0; t < 8; t++) g_idx[q * KSEL + t] = ti[t];
    #pragma unroll
    for (int i = 0; i < 8; i++) { tv[i] = -1e30f; ti[i] = 0; }
    for (int i = 0; i < NSPLIT * 8; i++) {
        float v = g_eucv[base + i];
        if (v > tv[7]) top8_insert(tv, ti, v, g_euci[base + i]);
    }
    #pragma unroll
    for (int t = 0; t < 8; t++) g_idx[q * KSEL + 8 + t] = ti[t];
}

// ---------------- fused GRU-mapping MLP ----------------
// block = 512 threads = 8 groups of 64; group handles one query, thread = channel o
#define GBAR(g) asm volatile("bar.sync %0, 64;" :: "r"((g) + 1) : "memory")

__global__ void __launch_bounds__(512) k_mlp(
    const float* __restrict__ xyz1, const float* __restrict__ xyz2,
    const float* __restrict__ Wr0, const float* __restrict__ br0,
    const float* __restrict__ Wr1, const float* __restrict__ br1,
    const float* __restrict__ Wr2, const float* __restrict__ br2,
    const float* __restrict__ Wz0, const float* __restrict__ bz0,
    const float* __restrict__ Wz1, const float* __restrict__ bz1,
    const float* __restrict__ Wz2, const float* __restrict__ bz2,
    const float* __restrict__ Wh0, const float* __restrict__ bh0,
    const float* __restrict__ Wh1, const float* __restrict__ bh1,
    const float* __restrict__ Wh2, const float* __restrict__ bh2,
    float* __restrict__ out)
{
    extern __shared__ __align__(16) float dsm[];
    float* WR1 = dsm;
    float* WR2 = WR1 + 4352;
    float* WZ1 = WR2 + 4352;
    float* WZ2 = WZ1 + 4352;
    float* WH1 = WZ2 + 4352;
    float* WH2 = WH1 + 4352;
    __shared__ __align__(16) float AB[8][2][68];
    __shared__ int sIdx[8 * 16];

    int tid = threadIdx.x;
    int g = tid >> 6, o = tid & 63;

    // load 6 weight matrices into padded smem rows
    {
        const float* Wsrc[6] = {Wr1, Wr2, Wz1, Wz2, Wh1, Wh2};
        for (int i = tid; i < 6 * 4096; i += 512) {
            int m = i >> 12, r = i & 4095;
            dsm[m * 4352 + (r >> 6) * 68 + (r & 63)] = Wsrc[m][r];
        }
    }

    int q = blockIdx.x * 8 + g;
    int b = q >> 12, n = q & 4095;
    if (o < 16) sIdx[g * 16 + o] = g_idx[q * KSEL + o];

    float wr0x = Wr0[o * 3], wr0y = Wr0[o * 3 + 1], wr0z = Wr0[o * 3 + 2];
    float wz0x = Wz0[o * 3], wz0y = Wz0[o * 3 + 1], wz0z = Wz0[o * 3 + 2];
    float wh0x = Wh0[o * 3], wh0y = Wh0[o * 3 + 1], wh0z = Wh0[o * 3 + 2];
    float br0o = br0[o], br1o = br1[o], br2o = br2[o];
    float bz0o = bz0[o], bz1o = bz1[o], bz2o = bz2[o];
    float bh0o = bh0[o], bh1o = bh1[o], bh2o = bh2[o];
    size_t nb = (size_t)b * N1 + n;
    float gp1ro = g_gp1r[nb * 64 + o];
    float gp1zo = g_gp1z[nb * 64 + o];
    float p1oo  = g_p1o [nb * 64 + o];
    float x1x = xyz1[(b * 3 + 0) * N1 + n];
    float x1y = xyz1[(b * 3 + 1) * N1 + n];
    float x1z = xyz1[(b * 3 + 2) * N1 + n];

    __syncthreads();

    float* A = AB[g][0];
    float* B = AB[g][1];

    // prefetch k=0
    int j = sIdx[g * 16];
    size_t gb = ((size_t)b * N2 + j) * 64 + o;
    float gr = g_p2r[gb], gro = g_p2ro[gb], gz = g_p2z[gb];
    float dxv = __ldg(&xyz2[(b * 3 + 0) * N2 + j]) - x1x;
    float dyv = __ldg(&xyz2[(b * 3 + 1) * N2 + j]) - x1y;
    float dzv = __ldg(&xyz2[(b * 3 + 2) * N2 + j]) - x1z;

    float zmax = -1e30f, hmax = -1e30f;

    #pragma unroll 1
    for (int k = 0; k < KSEL; k++) {
        float c_gr = gr, c_gro = gro, c_gz = gz;
        float cdx = dxv, cdy = dyv, cdz = dzv;
        if (k < KSEL - 1) {
            int jn = sIdx[g * 16 + k + 1];
            size_t gbn = ((size_t)b * N2 + jn) * 64 + o;
            gr = g_p2r[gbn]; gro = g_p2ro[gbn]; gz = g_p2z[gbn];
            dxv = __ldg(&xyz2[(b * 3 + 0) * N2 + jn]) - x1x;
            dyv = __ldg(&xyz2[(b * 3 + 1) * N2 + jn]) - x1y;
            dzv = __ldg(&xyz2[(b * 3 + 2) * N2 + jn]) - x1z;
        }
        float t0 = leaky(fmaf(wr0x, cdx, fmaf(wr0y, cdy, fmaf(wr0z, cdz, br0o + gp1ro + c_gr))));
        A[o] = t0;
        GBAR(g);
        float t1 = leaky(matvec64(WR1, A, o) + br1o);
        B[o] = t1;
        GBAR(g);
        float r = sigm(matvec64(WR2, B, o) + br2o);
        float u0 = leaky(fmaf(wz0x, cdx, fmaf(wz0y, cdy, fmaf(wz0z, cdz, bz0o + gp1zo + c_gro))));
        A[o] = u0;
        GBAR(g);
        float v0 = leaky(fmaf(wh0x, cdx, fmaf(wh0y, cdy, fmaf(wh0z, cdz, bh0o + fmaf(r, p1oo, c_gz)))));
        B[o] = v0;
        GBAR(g);
        zmax = fmaxf(zmax, leaky(matvec64(WZ1, A, o) + bz1o));
        hmax = fmaxf(hmax, leaky(matvec64(WH1, B, o) + bh1o));
        GBAR(g);
    }

    A[o] = zmax; B[o] = hmax;
    GBAR(g);
    float z = sigm(matvec64(WZ2, A, o) + bz2o);
    float h = leaky(matvec64(WH2, B, o) + bh2o);
    out[((size_t)b * 64 + o) * N1 + n] = (1.f - z) * p1oo + z * h;
}

// ---------------- launch ----------------
extern "C" void kernel_launch(void* const* d_in, const int* in_sizes, int n_in,
                              void* d_out, int out_size) {
    (void)in_sizes; (void)n_in; (void)out_size;
    const float* xyz1    = (const float*)d_in[0];
    const float* xyz2    = (const float*)d_in[1];
    const float* points1 = (const float*)d_in[2];
    const float* points2 = (const float*)d_in[3];
    const float* knn1    = (const float*)d_in[4];
    const float* knn2    = (const float*)d_in[5];
    const float* Wfr   = (const float*)d_in[6];
    const float* Wfro  = (const float*)d_in[7];
    const float* Wfz   = (const float*)d_in[8];
    const float* Wfr2  = (const float*)d_in[9];
    const float* Wfro2 = (const float*)d_in[10];
    const float* Wfz2  = (const float*)d_in[11];
    const float* Wr0 = (const float*)d_in[12]; const float* br0 = (const float*)d_in[13];
    const float* Wr1 = (const float*)d_in[14]; const float* br1 = (const float*)d_in[15];
    const float* Wr2 = (const float*)d_in[16]; const float* br2 = (const float*)d_in[17];
    const float* Wz0 = (const float*)d_in[18]; const float* bz0 = (const float*)d_in[19];
    const float* Wz1 = (const float*)d_in[20]; const float* bz1 = (const float*)d_in[21];
    const float* Wz2 = (const float*)d_in[22]; const float* bz2 = (const float*)d_in[23];
    const float* Wh0 = (const float*)d_in[24]; const float* bh0 = (const float*)d_in[25];
    const float* Wh1 = (const float*)d_in[26]; const float* bh1 = (const float*)d_in[27];
    const float* Wh2 = (const float*)d_in[28]; const float* bh2 = (const float*)d_in[29];
    float* out = (float*)d_out;

    float *f1n, *f2n, *p2r, *p2ro, *p2z, *gp1r, *gp1z, *p1o;
    cudaGetSymbolAddress((void**)&f1n,  g_f1n);
    cudaGetSymbolAddress((void**)&f2n,  g_f2n);
    cudaGetSymbolAddress((void**)&p2r,  g_p2r);
    cudaGetSymbolAddress((void**)&p2ro, g_p2ro);
    cudaGetSymbolAddress((void**)&p2z,  g_p2z);
    cudaGetSymbolAddress((void**)&gp1r, g_gp1r);
    cudaGetSymbolAddress((void**)&gp1z, g_gp1z);
    cudaGetSymbolAddress((void**)&p1o,  g_p1o);

    // normalize knn features (transposed layouts)
    k_normalize<<<dim3(N1 / 64, BB), 256>>>(knn1, f1n, N1);
    k_normalize<<<dim3(N2 / 64, BB), 256>>>(knn2, f2n, N2);

    // 6 fused 1x1-conv projections
    k_project<<<dim3(N2 / 64, BB), 256>>>(points2, Wfr2,  p2r,  N2);
    k_project<<<dim3(N2 / 64, BB), 256>>>(points2, Wfro2, p2ro, N2);
    k_project<<<dim3(N2 / 64, BB), 256>>>(points2, Wfz2,  p2z,  N2);
    k_project<<<dim3(N1 / 64, BB), 256>>>(points1, Wfr,   gp1r, N1);
    k_project<<<dim3(N1 / 64, BB), 256>>>(points1, Wfz,   gp1z, N1);
    k_project<<<dim3(N1 / 64, BB), 256>>>(points1, Wfro,  p1o,  N1);

    // knn selection
    k_cosknn<<<dim3(N1 / 128, NSPLIT, BB), 128>>>();
    k_eucknn<<<dim3(N1 / 128, NSPLIT, BB), 128>>>(xyz1, xyz2);
    k_merge<<<(BB * N1) / 256, 256>>>();

    // fused GRU MLP
    cudaFuncSetAttribute(k_mlp, cudaFuncAttributeMaxDynamicSharedMemorySize, 6 * 4352 * 4);
    k_mlp<<<(BB * N1) / 8, 512, 6 * 4352 * 4>>>(
        xyz1, xyz2,
        Wr0, br0, Wr1, br1, Wr2, br2,
        Wz0, bz0, Wz1, bz1, Wz2, bz2,
        Wh0, bh0, Wh1, bh1, Wh2, bh2,
        out);
}